// round 1
// baseline (speedup 1.0000x reference)
#include <cuda_runtime.h>
#include <cuda_bf16.h>
#include <cstdint>

// ---------------------------------------------------------------------------
// WeightPopupLayer: out = x @ (W * topk_mask(|scores|, 50%)).T + bias
//   x      [8192, 4096] f32   (d_in[0])
//   W      [4096, 4096] f32   (d_in[1])
//   bias   [4096]       f32   (d_in[2])
//   scores [4096, 4096] f32   (d_in[3])
//   out    [8192, 4096] f32
//
// Mask semantics (match jnp stable ascending argsort): flatten |scores|,
// drop the j = 8388608 smallest (ties broken by ascending flat index:
// lower-index ties dropped first), keep the rest.
// ---------------------------------------------------------------------------

#define NTOT   (4096 * 4096)
#define JRANK  8388608u          // int((1-K)*n), K = 0.5
#define EQ_CAP (1 << 22)         // capacity for threshold-tied indices

// Device scratch state (no cudaMalloc allowed)
__device__ float    g_pw[NTOT];          // pruned weights, 64 MB
__device__ unsigned g_hist[256];
__device__ unsigned g_prefix;            // radix-select prefix -> final = threshold bits
__device__ unsigned g_rank;              // residual rank -> final = #ties to drop
__device__ unsigned g_neq;               // number of tied entries found
__device__ unsigned g_idxcut;            // keep tie iff flat_index >= g_idxcut
__device__ unsigned g_eqidx[EQ_CAP];

static __device__ __forceinline__ unsigned abs_bits(float v) {
    // |v| >= 0 -> uint bit pattern is order-isomorphic to float value
    return __float_as_uint(fabsf(v));
}

// ---- 1. init --------------------------------------------------------------
__global__ void k_init() {
    int t = threadIdx.x;
    if (t < 256) g_hist[t] = 0;
    if (t == 0) { g_prefix = 0u; g_rank = JRANK; g_neq = 0u; g_idxcut = 0u; }
}

// ---- 2. radix-select histogram pass (MSB-first, 8 bits/pass) ---------------
__global__ void k_hist(const float* __restrict__ s, int n, int shift) {
    __shared__ unsigned sh[256];
    if (threadIdx.x < 256) sh[threadIdx.x] = 0;
    __syncthreads();
    const unsigned pref = g_prefix;
    const unsigned mask = (shift == 24) ? 0u : (0xFFFFFFFFu << (shift + 8));
    int stride = blockDim.x * gridDim.x;
    for (int i = blockIdx.x * blockDim.x + threadIdx.x; i < n; i += stride) {
        unsigned b = abs_bits(s[i]);
        if ((b & mask) == pref)
            atomicAdd(&sh[(b >> shift) & 0xFF], 1u);
    }
    __syncthreads();
    if (threadIdx.x < 256 && sh[threadIdx.x])
        atomicAdd(&g_hist[threadIdx.x], sh[threadIdx.x]);
}

// ---- 3. pick winning bin, narrow prefix, reset hist -------------------------
__global__ void k_pick(int shift) {
    unsigned r = g_rank, cum = 0;
    #pragma unroll 1
    for (int b = 0; b < 256; ++b) {
        unsigned c = g_hist[b];
        if (cum + c > r) {
            g_prefix |= ((unsigned)b) << shift;
            g_rank = r - cum;
            break;
        }
        cum += c;
    }
    for (int b = 0; b < 256; ++b) g_hist[b] = 0;
}

// ---- 4. gather flat indices of entries exactly at the threshold ------------
__global__ void k_gather(const float* __restrict__ s, int n) {
    const unsigned tb = g_prefix;
    int stride = blockDim.x * gridDim.x;
    for (int i = blockIdx.x * blockDim.x + threadIdx.x; i < n; i += stride) {
        if (abs_bits(s[i]) == tb) {
            unsigned p = atomicAdd(&g_neq, 1u);
            if (p < EQ_CAP) g_eqidx[p] = (unsigned)i;
        }
    }
}

// ---- 5. index cutoff among ties: drop the g_rank smallest indices ----------
__global__ void k_select_cut() {
    unsigned m = min(g_neq, (unsigned)EQ_CAP);
    unsigned d = g_rank;                 // how many ties to drop
    if (threadIdx.x == 0) {
        if (d == 0u) g_idxcut = 0u;      // keep all ties
        else if (d >= m) g_idxcut = 0xFFFFFFFFu; // keep none
    }
    if (d == 0u || d >= m) return;
    for (unsigned e = threadIdx.x; e < m; e += blockDim.x) {
        unsigned v = g_eqidx[e];
        unsigned rank = 0;
        for (unsigned f = 0; f < m; ++f) rank += (g_eqidx[f] < v);
        if (rank == d) g_idxcut = v;     // unique writer (indices distinct)
    }
}

// ---- 6. build pruned weights ------------------------------------------------
__global__ void k_prune(const float* __restrict__ w, const float* __restrict__ s, int n) {
    const unsigned tb  = g_prefix;
    const unsigned cut = g_idxcut;
    int stride = blockDim.x * gridDim.x;
    int n4 = n >> 2;
    const float4* s4 = (const float4*)s;
    const float4* w4 = (const float4*)w;
    float4*       p4 = (float4*)g_pw;
    for (int i = blockIdx.x * blockDim.x + threadIdx.x; i < n4; i += stride) {
        float4 sv = s4[i], wv = w4[i], out;
        unsigned base = (unsigned)i << 2;
        unsigned b0 = abs_bits(sv.x), b1 = abs_bits(sv.y),
                 b2 = abs_bits(sv.z), b3 = abs_bits(sv.w);
        out.x = (b0 > tb || (b0 == tb && base + 0 >= cut)) ? wv.x : 0.0f;
        out.y = (b1 > tb || (b1 == tb && base + 1 >= cut)) ? wv.y : 0.0f;
        out.z = (b2 > tb || (b2 == tb && base + 2 >= cut)) ? wv.z : 0.0f;
        out.w = (b3 > tb || (b3 == tb && base + 3 >= cut)) ? wv.w : 0.0f;
        p4[i] = out;
    }
}

// ---- 7. GEMM: C[M,N] = A[M,K] * Bw[N,K]^T + bias ----------------------------
// 128x128 block tile, BK=16, 8x8 per thread, 256 threads, padded smem.
#define BM 128
#define BN 128
#define BKD 16
#define TM 8
#define TN 8

__global__ void __launch_bounds__(256)
k_gemm(const float* __restrict__ A, const float* __restrict__ bias,
       float* __restrict__ C, int M, int N, int Kd) {
    __shared__ __align__(16) float As[BKD][BM + 4];
    __shared__ __align__(16) float Bs[BKD][BN + 4];

    const float* Bw = g_pw;
    const int bx = blockIdx.x;           // N tile
    const int by = blockIdx.y;           // M tile
    const int tid = threadIdx.x;
    const int tx = tid & 15;             // 0..15 -> N
    const int ty = tid >> 4;             // 0..15 -> M

    const int lrow = tid >> 2;           // 0..63
    const int lcol = (tid & 3) << 2;     // 0,4,8,12

    const float* Aptr = A  + (size_t)(by * BM) * Kd;
    const float* Bptr = Bw + (size_t)(bx * BN) * Kd;

    float acc[TM][TN];
    #pragma unroll
    for (int i = 0; i < TM; ++i)
        #pragma unroll
        for (int j = 0; j < TN; ++j) acc[i][j] = 0.0f;

    for (int k0 = 0; k0 < Kd; k0 += BKD) {
        #pragma unroll
        for (int r = 0; r < 2; ++r) {
            int row = lrow + r * 64;
            float4 va = *(const float4*)(Aptr + (size_t)row * Kd + k0 + lcol);
            As[lcol + 0][row] = va.x; As[lcol + 1][row] = va.y;
            As[lcol + 2][row] = va.z; As[lcol + 3][row] = va.w;
            float4 vb = *(const float4*)(Bptr + (size_t)row * Kd + k0 + lcol);
            Bs[lcol + 0][row] = vb.x; Bs[lcol + 1][row] = vb.y;
            Bs[lcol + 2][row] = vb.z; Bs[lcol + 3][row] = vb.w;
        }
        __syncthreads();

        #pragma unroll
        for (int kk = 0; kk < BKD; ++kk) {
            float a[TM], b[TN];
            *(float4*)&a[0] = *(const float4*)&As[kk][ty * TM];
            *(float4*)&a[4] = *(const float4*)&As[kk][ty * TM + 4];
            *(float4*)&b[0] = *(const float4*)&Bs[kk][tx * TN];
            *(float4*)&b[4] = *(const float4*)&Bs[kk][tx * TN + 4];
            #pragma unroll
            for (int i = 0; i < TM; ++i)
                #pragma unroll
                for (int j = 0; j < TN; ++j)
                    acc[i][j] = fmaf(a[i], b[j], acc[i][j]);
        }
        __syncthreads();
    }

    // epilogue: add bias, vectorized stores
    const int crow0 = by * BM + ty * TM;
    const int ccol0 = bx * BN + tx * TN;
    float bv[TN];
    *(float4*)&bv[0] = *(const float4*)(bias + ccol0);
    *(float4*)&bv[4] = *(const float4*)(bias + ccol0 + 4);
    #pragma unroll
    for (int i = 0; i < TM; ++i) {
        float4 o0, o1;
        o0.x = acc[i][0] + bv[0]; o0.y = acc[i][1] + bv[1];
        o0.z = acc[i][2] + bv[2]; o0.w = acc[i][3] + bv[3];
        o1.x = acc[i][4] + bv[4]; o1.y = acc[i][5] + bv[5];
        o1.z = acc[i][6] + bv[6]; o1.w = acc[i][7] + bv[7];
        float* crow = C + (size_t)(crow0 + i) * N + ccol0;
        *(float4*)(crow)     = o0;
        *(float4*)(crow + 4) = o1;
    }
}

// ---------------------------------------------------------------------------
extern "C" void kernel_launch(void* const* d_in, const int* in_sizes, int n_in,
                              void* d_out, int out_size) {
    const float* x    = (const float*)d_in[0];
    const float* w    = (const float*)d_in[1];
    const float* bias = (const float*)d_in[2];
    const float* s    = (const float*)d_in[3];
    float* out = (float*)d_out;

    const int M = 8192, N = 4096, K = 4096;

    k_init<<<1, 256>>>();
    for (int shift = 24; shift >= 0; shift -= 8) {
        k_hist<<<1024, 256>>>(s, NTOT, shift);
        k_pick<<<1, 1>>>(shift);
    }
    k_gather<<<1024, 256>>>(s, NTOT);
    k_select_cut<<<1, 256>>>();
    k_prune<<<2048, 256>>>(w, s, NTOT);

    dim3 grid(N / BN, M / BM);   // 32 x 64
    k_gemm<<<grid, 256>>>(x, bias, out, M, N, K);
}

// round 3
// speedup vs baseline: 2.3023x; 2.3023x over previous
#include <cuda_runtime.h>
#include <cuda_bf16.h>
#include <cstdint>

// ===========================================================================
// WeightPopupLayer: out = x @ (W * topk_mask(|scores|, 50%)).T + bias
// Plan: exact radix-select threshold (+ stable-argsort tie handling),
//       bf16 hi/lo split of x and masked W,
//       mma.sync bf16 GEMM (3 combos: hh, hl, lh) with fp32 accum.
// (tcgen05 is unavailable: harness compiles PTX with .target sm_103, which
//  rejects all sm_103a-gated instructions.)
// ===========================================================================

#define NTOT   (4096 * 4096)
#define JRANK  8388608u
#define EQ_CAP (1 << 20)

#define M_DIM 8192
#define N_DIM 4096
#define K_DIM 4096

// ---- device scratch (no cudaMalloc allowed) ----
__device__ __align__(16) __nv_bfloat16 g_ah[M_DIM * K_DIM];   // 64 MB
__device__ __align__(16) __nv_bfloat16 g_al[M_DIM * K_DIM];   // 64 MB
__device__ __align__(16) __nv_bfloat16 g_bh[N_DIM * K_DIM];   // 32 MB
__device__ __align__(16) __nv_bfloat16 g_bl[N_DIM * K_DIM];   // 32 MB

__device__ unsigned g_hist[256];
__device__ unsigned g_prefix;
__device__ unsigned g_rank;
__device__ unsigned g_neq;
__device__ unsigned g_idxcut;
__device__ unsigned g_eqidx[EQ_CAP];

static __device__ __forceinline__ unsigned abs_bits(float v) {
    return __float_as_uint(fabsf(v));
}

// ======================= selection kernels =================================
__global__ void k_init() {
    int t = threadIdx.x;
    if (t < 256) g_hist[t] = 0;
    if (t == 0) { g_prefix = 0u; g_rank = JRANK; g_neq = 0u; g_idxcut = 0u; }
}

__global__ void k_hist(const float4* __restrict__ s4, int n4, int shift) {
    __shared__ unsigned sh[256];
    if (threadIdx.x < 256) sh[threadIdx.x] = 0;
    __syncthreads();
    const unsigned pref = g_prefix;
    const unsigned mask = (shift == 24) ? 0u : (0xFFFFFFFFu << (shift + 8));
    int stride = blockDim.x * gridDim.x;
    for (int i = blockIdx.x * blockDim.x + threadIdx.x; i < n4; i += stride) {
        float4 v = s4[i];
        unsigned b;
        b = abs_bits(v.x); if ((b & mask) == pref) atomicAdd(&sh[(b >> shift) & 255], 1u);
        b = abs_bits(v.y); if ((b & mask) == pref) atomicAdd(&sh[(b >> shift) & 255], 1u);
        b = abs_bits(v.z); if ((b & mask) == pref) atomicAdd(&sh[(b >> shift) & 255], 1u);
        b = abs_bits(v.w); if ((b & mask) == pref) atomicAdd(&sh[(b >> shift) & 255], 1u);
    }
    __syncthreads();
    if (threadIdx.x < 256 && sh[threadIdx.x])
        atomicAdd(&g_hist[threadIdx.x], sh[threadIdx.x]);
}

__global__ void k_pick(int shift) {
    unsigned r = g_rank, cum = 0;
    #pragma unroll 1
    for (int b = 0; b < 256; ++b) {
        unsigned c = g_hist[b];
        if (cum + c > r) { g_prefix |= ((unsigned)b) << shift; g_rank = r - cum; break; }
        cum += c;
    }
    for (int b = 0; b < 256; ++b) g_hist[b] = 0;
}

__global__ void k_gather(const float4* __restrict__ s4, int n4) {
    const unsigned tb = g_prefix;
    int stride = blockDim.x * gridDim.x;
    for (int i = blockIdx.x * blockDim.x + threadIdx.x; i < n4; i += stride) {
        float4 v = s4[i];
        unsigned base = (unsigned)i << 2;
        if (abs_bits(v.x) == tb) { unsigned p = atomicAdd(&g_neq, 1u); if (p < EQ_CAP) g_eqidx[p] = base + 0; }
        if (abs_bits(v.y) == tb) { unsigned p = atomicAdd(&g_neq, 1u); if (p < EQ_CAP) g_eqidx[p] = base + 1; }
        if (abs_bits(v.z) == tb) { unsigned p = atomicAdd(&g_neq, 1u); if (p < EQ_CAP) g_eqidx[p] = base + 2; }
        if (abs_bits(v.w) == tb) { unsigned p = atomicAdd(&g_neq, 1u); if (p < EQ_CAP) g_eqidx[p] = base + 3; }
    }
}

__global__ void k_select_cut() {
    unsigned m = min(g_neq, (unsigned)EQ_CAP);
    unsigned d = g_rank;
    if (threadIdx.x == 0) {
        if (d == 0u) g_idxcut = 0u;
        else if (d >= m) g_idxcut = 0xFFFFFFFFu;
    }
    if (d == 0u || d >= m) return;
    for (unsigned e = threadIdx.x; e < m; e += blockDim.x) {
        unsigned v = g_eqidx[e];
        unsigned rank = 0;
        for (unsigned f = 0; f < m; ++f) rank += (g_eqidx[f] < v);
        if (rank == d) g_idxcut = v;
    }
}

// ======================= split kernels =====================================
static __device__ __forceinline__ void split1(float f, unsigned short& h, unsigned short& l) {
    __nv_bfloat16 hh = __float2bfloat16(f);
    __nv_bfloat16 ll = __float2bfloat16(f - __bfloat162float(hh));
    h = __bfloat16_as_ushort(hh);
    l = __bfloat16_as_ushort(ll);
}

__global__ void k_split_w(const float4* __restrict__ w4, const float4* __restrict__ s4, int n4) {
    const unsigned tb  = g_prefix;
    const unsigned cut = g_idxcut;
    int stride = blockDim.x * gridDim.x;
    uint2* bh2 = (uint2*)g_bh;
    uint2* bl2 = (uint2*)g_bl;
    for (int i = blockIdx.x * blockDim.x + threadIdx.x; i < n4; i += stride) {
        float4 wv = w4[i], sv = s4[i];
        unsigned base = (unsigned)i << 2;
        float f[4];
        unsigned b0 = abs_bits(sv.x), b1 = abs_bits(sv.y), b2 = abs_bits(sv.z), b3 = abs_bits(sv.w);
        f[0] = (b0 > tb || (b0 == tb && base + 0 >= cut)) ? wv.x : 0.0f;
        f[1] = (b1 > tb || (b1 == tb && base + 1 >= cut)) ? wv.y : 0.0f;
        f[2] = (b2 > tb || (b2 == tb && base + 2 >= cut)) ? wv.z : 0.0f;
        f[3] = (b3 > tb || (b3 == tb && base + 3 >= cut)) ? wv.w : 0.0f;
        unsigned short h[4], l[4];
        #pragma unroll
        for (int c = 0; c < 4; ++c) split1(f[c], h[c], l[c]);
        uint2 ph, pl;
        ph.x = (unsigned)h[0] | ((unsigned)h[1] << 16);
        ph.y = (unsigned)h[2] | ((unsigned)h[3] << 16);
        pl.x = (unsigned)l[0] | ((unsigned)l[1] << 16);
        pl.y = (unsigned)l[2] | ((unsigned)l[3] << 16);
        bh2[i] = ph; bl2[i] = pl;
    }
}

__global__ void k_split_a(const float4* __restrict__ x4, int n4) {
    int stride = blockDim.x * gridDim.x;
    uint2* ah2 = (uint2*)g_ah;
    uint2* al2 = (uint2*)g_al;
    for (int i = blockIdx.x * blockDim.x + threadIdx.x; i < n4; i += stride) {
        float4 v = x4[i];
        float f[4] = {v.x, v.y, v.z, v.w};
        unsigned short h[4], l[4];
        #pragma unroll
        for (int c = 0; c < 4; ++c) split1(f[c], h[c], l[c]);
        uint2 ph, pl;
        ph.x = (unsigned)h[0] | ((unsigned)h[1] << 16);
        ph.y = (unsigned)h[2] | ((unsigned)h[3] << 16);
        pl.x = (unsigned)l[0] | ((unsigned)l[1] << 16);
        pl.y = (unsigned)l[2] | ((unsigned)l[3] << 16);
        ah2[i] = ph; al2[i] = pl;
    }
}

// ======================= mma.sync bf16 GEMM ================================
// C[128,128] per CTA; BK = 32; 8 warps (2 x 4), warp tile 64 x 32.
// smem per stage: 4 matrices (Ah, Al, Bh, Bl), 128 rows x 32 bf16, row
// stride 80 B (pad) -> 10240 B each, 40960 B per stage, 2 stages = 81920 B.

#define BK          32
#define ROW_BYTES   80
#define MAT_BYTES   (128 * ROW_BYTES)       // 10240
#define STAGE_BYTES (4 * MAT_BYTES)         // 40960
#define SMEM_GEMM   (2 * STAGE_BYTES)       // 81920
#define KSTEPS      (K_DIM / BK)            // 128

#define CP_COMMIT() asm volatile("cp.async.commit_group;\n" ::: "memory")
#define CP_WAIT(n)  asm volatile("cp.async.wait_group %0;\n" :: "n"(n) : "memory")

static __device__ __forceinline__ void cp16(uint32_t dst, const void* src) {
    asm volatile("cp.async.cg.shared.global [%0], [%1], 16;\n" :: "r"(dst), "l"(src));
}

#define LDSM4(r0, r1, r2, r3, addr) \
    asm volatile("ldmatrix.sync.aligned.m8n8.x4.shared.b16 {%0,%1,%2,%3}, [%4];" \
                 : "=r"(r0), "=r"(r1), "=r"(r2), "=r"(r3) : "r"(addr))

#define MMA_BF16(d, a0, a1, a2, a3, b0, b1) \
    asm volatile("mma.sync.aligned.m16n8k16.row.col.f32.bf16.bf16.f32 " \
                 "{%0,%1,%2,%3}, {%4,%5,%6,%7}, {%8,%9}, {%0,%1,%2,%3};" \
                 : "+f"((d)[0]), "+f"((d)[1]), "+f"((d)[2]), "+f"((d)[3]) \
                 : "r"(a0), "r"(a1), "r"(a2), "r"(a3), "r"(b0), "r"(b1))

static __device__ __forceinline__ void load_stage(
    uint32_t sb, int slot, int tid,
    const char* gah, const char* gal, const char* gbh, const char* gbl, int kstep) {
    uint32_t base = sb + (uint32_t)slot * STAGE_BYTES;
    size_t kbyte = (size_t)kstep * (BK * 2);
    #pragma unroll
    for (int i = 0; i < 2; ++i) {
        int c = tid + i * 256;               // 512 chunks of 16B per matrix
        int row = c >> 2, colb = (c & 3) * 16;
        uint32_t soff = (uint32_t)row * ROW_BYTES + colb;
        size_t goff = (size_t)row * (K_DIM * 2) + kbyte + colb;
        cp16(base + 0 * MAT_BYTES + soff, gah + goff);
        cp16(base + 1 * MAT_BYTES + soff, gal + goff);
        cp16(base + 2 * MAT_BYTES + soff, gbh + goff);
        cp16(base + 3 * MAT_BYTES + soff, gbl + goff);
    }
}

__global__ void __launch_bounds__(256, 1)
k_gemm(const float* __restrict__ bias, float* __restrict__ outp) {
    extern __shared__ char dsmem[];
    uint32_t sb;
    asm("{ .reg .u64 t; cvta.to.shared.u64 t, %1; cvt.u32.u64 %0, t; }"
        : "=r"(sb) : "l"(dsmem));

    const int tid  = threadIdx.x;
    const int wid  = tid >> 5;
    const int lane = tid & 31;
    const int bx = blockIdx.x;               // N tile (0..31)
    const int by = blockIdx.y;               // M tile (0..63)
    const int wm = wid >> 2;                 // 0..1
    const int wn = wid & 3;                  // 0..3

    const char* gah = (const char*)(g_ah + (size_t)by * 128 * K_DIM);
    const char* gal = (const char*)(g_al + (size_t)by * 128 * K_DIM);
    const char* gbh = (const char*)(g_bh + (size_t)bx * 128 * K_DIM);
    const char* gbl = (const char*)(g_bl + (size_t)bx * 128 * K_DIM);

    // ldmatrix lane-address offsets (relative to matrix base within a stage)
    // A (x4 covering m16 x k16): lanes 0-15 rows m0-15 byte 0; 16-31 rows +16B
    uint32_t offA[4];
    {
        int arow = wm * 64 + (lane & 15);
        int abyte = (lane >> 4) * 16;
        #pragma unroll
        for (int mt = 0; mt < 4; ++mt)
            offA[mt] = (uint32_t)(arow + mt * 16) * ROW_BYTES + abyte;
    }
    // B (x4 covering n16 x k16): g0: n0-7 b0; g1: n0-7 b16; g2: n8-15 b0; g3: n8-15 b16
    uint32_t offB[2];
    {
        int brow_lo = ((lane >> 4) << 3) + (lane & 7);
        int bbyte = ((lane >> 3) & 1) * 16;
        #pragma unroll
        for (int p = 0; p < 2; ++p)
            offB[p] = (uint32_t)(wn * 32 + p * 16 + brow_lo) * ROW_BYTES + bbyte;
    }

    float acc[4][4][4];
    #pragma unroll
    for (int i = 0; i < 4; ++i)
        #pragma unroll
        for (int j = 0; j < 4; ++j)
            #pragma unroll
            for (int e = 0; e < 4; ++e) acc[i][j][e] = 0.0f;

    load_stage(sb, 0, tid, gah, gal, gbh, gbl, 0);
    CP_COMMIT();

    #pragma unroll 1
    for (int s = 0; s < KSTEPS; ++s) {
        if (s + 1 < KSTEPS) {
            load_stage(sb, (s + 1) & 1, tid, gah, gal, gbh, gbl, s + 1);
            CP_COMMIT();
            CP_WAIT(1);
        } else {
            CP_WAIT(0);
        }
        __syncthreads();

        uint32_t mbase = sb + (uint32_t)(s & 1) * STAGE_BYTES;
        #pragma unroll
        for (int ks = 0; ks < 2; ++ks) {
            uint32_t kb = (uint32_t)ks * 32;
            uint32_t ah[4][4], al[4][4], bh[2][4], bl[2][4];
            #pragma unroll
            for (int mt = 0; mt < 4; ++mt) {
                uint32_t a = mbase + offA[mt] + kb;
                LDSM4(ah[mt][0], ah[mt][1], ah[mt][2], ah[mt][3], a + 0 * MAT_BYTES);
                LDSM4(al[mt][0], al[mt][1], al[mt][2], al[mt][3], a + 1 * MAT_BYTES);
            }
            #pragma unroll
            for (int p = 0; p < 2; ++p) {
                uint32_t b = mbase + offB[p] + kb;
                LDSM4(bh[p][0], bh[p][1], bh[p][2], bh[p][3], b + 2 * MAT_BYTES);
                LDSM4(bl[p][0], bl[p][1], bl[p][2], bl[p][3], b + 3 * MAT_BYTES);
            }
            #pragma unroll
            for (int mt = 0; mt < 4; ++mt) {
                #pragma unroll
                for (int p = 0; p < 2; ++p) {
                    float* d0 = acc[mt][2 * p];
                    float* d1 = acc[mt][2 * p + 1];
                    MMA_BF16(d0, ah[mt][0], ah[mt][1], ah[mt][2], ah[mt][3], bh[p][0], bh[p][1]);
                    MMA_BF16(d1, ah[mt][0], ah[mt][1], ah[mt][2], ah[mt][3], bh[p][2], bh[p][3]);
                    MMA_BF16(d0, ah[mt][0], ah[mt][1], ah[mt][2], ah[mt][3], bl[p][0], bl[p][1]);
                    MMA_BF16(d1, ah[mt][0], ah[mt][1], ah[mt][2], ah[mt][3], bl[p][2], bl[p][3]);
                    MMA_BF16(d0, al[mt][0], al[mt][1], al[mt][2], al[mt][3], bh[p][0], bh[p][1]);
                    MMA_BF16(d1, al[mt][0], al[mt][1], al[mt][2], al[mt][3], bh[p][2], bh[p][3]);
                }
            }
        }
        __syncthreads();
    }

    // ---- epilogue: add bias, store fp32 ----
    #pragma unroll
    for (int nt = 0; nt < 4; ++nt) {
        int col = bx * 128 + wn * 32 + nt * 8 + (lane & 3) * 2;
        float2 bv = *(const float2*)(bias + col);
        #pragma unroll
        for (int mt = 0; mt < 4; ++mt) {
            int r0 = by * 128 + wm * 64 + mt * 16 + (lane >> 2);
            float2 o0, o1;
            o0.x = acc[mt][nt][0] + bv.x; o0.y = acc[mt][nt][1] + bv.y;
            o1.x = acc[mt][nt][2] + bv.x; o1.y = acc[mt][nt][3] + bv.y;
            *(float2*)(outp + (size_t)r0 * N_DIM + col)       = o0;
            *(float2*)(outp + (size_t)(r0 + 8) * N_DIM + col) = o1;
        }
    }
}

// ===========================================================================
extern "C" void kernel_launch(void* const* d_in, const int* in_sizes, int n_in,
                              void* d_out, int out_size) {
    const float* x    = (const float*)d_in[0];
    const float* w    = (const float*)d_in[1];
    const float* bias = (const float*)d_in[2];
    const float* s    = (const float*)d_in[3];
    float* out = (float*)d_out;

    k_init<<<1, 256>>>();
    for (int shift = 24; shift >= 0; shift -= 8) {
        k_hist<<<1024, 256>>>((const float4*)s, NTOT / 4, shift);
        k_pick<<<1, 1>>>(shift);
    }
    k_gather<<<1024, 256>>>((const float4*)s, NTOT / 4);
    k_select_cut<<<1, 256>>>();

    k_split_w<<<2048, 256>>>((const float4*)w, (const float4*)s, NTOT / 4);
    k_split_a<<<4096, 256>>>((const float4*)x, (M_DIM * K_DIM) / 4);

    cudaFuncSetAttribute(k_gemm, cudaFuncAttributeMaxDynamicSharedMemorySize, SMEM_GEMM);
    dim3 grid(N_DIM / 128, M_DIM / 128);   // 32 x 64
    k_gemm<<<grid, 256, SMEM_GEMM>>>(bias, out);
}

// round 4
// speedup vs baseline: 2.7406x; 1.1904x over previous
#include <cuda_runtime.h>
#include <cuda_bf16.h>
#include <cstdint>

// ===========================================================================
// WeightPopupLayer: out = x @ (W * topk_mask(|scores|, 50%)).T + bias
// Round 4: 256x128 CTA tile, 512 threads, 3-stage cp.async ring (prefetch
// distance 2), bf16 hi/lo 3-term mma.sync GEMM with fp32 accumulators.
// ===========================================================================

#define NTOT   (4096 * 4096)
#define JRANK  8388608u
#define EQ_CAP (1 << 20)

#define M_DIM 8192
#define N_DIM 4096
#define K_DIM 4096

// ---- device scratch (no cudaMalloc allowed) ----
__device__ __align__(16) __nv_bfloat16 g_ah[M_DIM * K_DIM];   // 64 MB
__device__ __align__(16) __nv_bfloat16 g_al[M_DIM * K_DIM];   // 64 MB
__device__ __align__(16) __nv_bfloat16 g_bh[N_DIM * K_DIM];   // 32 MB
__device__ __align__(16) __nv_bfloat16 g_bl[N_DIM * K_DIM];   // 32 MB

__device__ unsigned g_hist[256];
__device__ unsigned g_prefix;
__device__ unsigned g_rank;
__device__ unsigned g_neq;
__device__ unsigned g_idxcut;
__device__ unsigned g_eqidx[EQ_CAP];

static __device__ __forceinline__ unsigned abs_bits(float v) {
    return __float_as_uint(fabsf(v));
}

// ======================= selection kernels =================================
__global__ void k_init() {
    int t = threadIdx.x;
    if (t < 256) g_hist[t] = 0;
    if (t == 0) { g_prefix = 0u; g_rank = JRANK; g_neq = 0u; g_idxcut = 0u; }
}

__global__ void k_hist(const float4* __restrict__ s4, int n4, int shift) {
    __shared__ unsigned sh[256];
    if (threadIdx.x < 256) sh[threadIdx.x] = 0;
    __syncthreads();
    const unsigned pref = g_prefix;
    const unsigned mask = (shift == 24) ? 0u : (0xFFFFFFFFu << (shift + 8));
    int stride = blockDim.x * gridDim.x;
    for (int i = blockIdx.x * blockDim.x + threadIdx.x; i < n4; i += stride) {
        float4 v = s4[i];
        unsigned b;
        b = abs_bits(v.x); if ((b & mask) == pref) atomicAdd(&sh[(b >> shift) & 255], 1u);
        b = abs_bits(v.y); if ((b & mask) == pref) atomicAdd(&sh[(b >> shift) & 255], 1u);
        b = abs_bits(v.z); if ((b & mask) == pref) atomicAdd(&sh[(b >> shift) & 255], 1u);
        b = abs_bits(v.w); if ((b & mask) == pref) atomicAdd(&sh[(b >> shift) & 255], 1u);
    }
    __syncthreads();
    if (threadIdx.x < 256 && sh[threadIdx.x])
        atomicAdd(&g_hist[threadIdx.x], sh[threadIdx.x]);
}

__global__ void k_pick(int shift) {
    unsigned r = g_rank, cum = 0;
    #pragma unroll 1
    for (int b = 0; b < 256; ++b) {
        unsigned c = g_hist[b];
        if (cum + c > r) { g_prefix |= ((unsigned)b) << shift; g_rank = r - cum; break; }
        cum += c;
    }
    for (int b = 0; b < 256; ++b) g_hist[b] = 0;
}

__global__ void k_gather(const float4* __restrict__ s4, int n4) {
    const unsigned tb = g_prefix;
    int stride = blockDim.x * gridDim.x;
    for (int i = blockIdx.x * blockDim.x + threadIdx.x; i < n4; i += stride) {
        float4 v = s4[i];
        unsigned base = (unsigned)i << 2;
        if (abs_bits(v.x) == tb) { unsigned p = atomicAdd(&g_neq, 1u); if (p < EQ_CAP) g_eqidx[p] = base + 0; }
        if (abs_bits(v.y) == tb) { unsigned p = atomicAdd(&g_neq, 1u); if (p < EQ_CAP) g_eqidx[p] = base + 1; }
        if (abs_bits(v.z) == tb) { unsigned p = atomicAdd(&g_neq, 1u); if (p < EQ_CAP) g_eqidx[p] = base + 2; }
        if (abs_bits(v.w) == tb) { unsigned p = atomicAdd(&g_neq, 1u); if (p < EQ_CAP) g_eqidx[p] = base + 3; }
    }
}

__global__ void k_select_cut() {
    unsigned m = min(g_neq, (unsigned)EQ_CAP);
    unsigned d = g_rank;
    if (threadIdx.x == 0) {
        if (d == 0u) g_idxcut = 0u;
        else if (d >= m) g_idxcut = 0xFFFFFFFFu;
    }
    if (d == 0u || d >= m) return;
    for (unsigned e = threadIdx.x; e < m; e += blockDim.x) {
        unsigned v = g_eqidx[e];
        unsigned rank = 0;
        for (unsigned f = 0; f < m; ++f) rank += (g_eqidx[f] < v);
        if (rank == d) g_idxcut = v;
    }
}

// ======================= split kernels =====================================
static __device__ __forceinline__ void split1(float f, unsigned short& h, unsigned short& l) {
    __nv_bfloat16 hh = __float2bfloat16(f);
    __nv_bfloat16 ll = __float2bfloat16(f - __bfloat162float(hh));
    h = __bfloat16_as_ushort(hh);
    l = __bfloat16_as_ushort(ll);
}

__global__ void k_split_w(const float4* __restrict__ w4, const float4* __restrict__ s4, int n4) {
    const unsigned tb  = g_prefix;
    const unsigned cut = g_idxcut;
    int stride = blockDim.x * gridDim.x;
    uint2* bh2 = (uint2*)g_bh;
    uint2* bl2 = (uint2*)g_bl;
    for (int i = blockIdx.x * blockDim.x + threadIdx.x; i < n4; i += stride) {
        float4 wv = w4[i], sv = s4[i];
        unsigned base = (unsigned)i << 2;
        float f[4];
        unsigned b0 = abs_bits(sv.x), b1 = abs_bits(sv.y), b2 = abs_bits(sv.z), b3 = abs_bits(sv.w);
        f[0] = (b0 > tb || (b0 == tb && base + 0 >= cut)) ? wv.x : 0.0f;
        f[1] = (b1 > tb || (b1 == tb && base + 1 >= cut)) ? wv.y : 0.0f;
        f[2] = (b2 > tb || (b2 == tb && base + 2 >= cut)) ? wv.z : 0.0f;
        f[3] = (b3 > tb || (b3 == tb && base + 3 >= cut)) ? wv.w : 0.0f;
        unsigned short h[4], l[4];
        #pragma unroll
        for (int c = 0; c < 4; ++c) split1(f[c], h[c], l[c]);
        uint2 ph, pl;
        ph.x = (unsigned)h[0] | ((unsigned)h[1] << 16);
        ph.y = (unsigned)h[2] | ((unsigned)h[3] << 16);
        pl.x = (unsigned)l[0] | ((unsigned)l[1] << 16);
        pl.y = (unsigned)l[2] | ((unsigned)l[3] << 16);
        bh2[i] = ph; bl2[i] = pl;
    }
}

__global__ void k_split_a(const float4* __restrict__ x4, int n4) {
    int stride = blockDim.x * gridDim.x;
    uint2* ah2 = (uint2*)g_ah;
    uint2* al2 = (uint2*)g_al;
    for (int i = blockIdx.x * blockDim.x + threadIdx.x; i < n4; i += stride) {
        float4 v = x4[i];
        float f[4] = {v.x, v.y, v.z, v.w};
        unsigned short h[4], l[4];
        #pragma unroll
        for (int c = 0; c < 4; ++c) split1(f[c], h[c], l[c]);
        uint2 ph, pl;
        ph.x = (unsigned)h[0] | ((unsigned)h[1] << 16);
        ph.y = (unsigned)h[2] | ((unsigned)h[3] << 16);
        pl.x = (unsigned)l[0] | ((unsigned)l[1] << 16);
        pl.y = (unsigned)l[2] | ((unsigned)l[3] << 16);
        ah2[i] = ph; al2[i] = pl;
    }
}

// ======================= mma.sync bf16 GEMM ================================
// CTA tile 256(M) x 128(N); BK = 32; 512 threads = 16 warps (4x4),
// warp tile 64x32. smem per stage: Ah/Al 256x32 bf16 (row stride 80B) +
// Bh/Bl 128x32 bf16 -> 61440 B; 3-stage ring = 184320 B.

#define BK          32
#define ROW_BYTES   80
#define A_MAT_BYTES (256 * ROW_BYTES)       // 20480
#define B_MAT_BYTES (128 * ROW_BYTES)       // 10240
#define SM_AH       0
#define SM_AL       (A_MAT_BYTES)
#define SM_BH       (2 * A_MAT_BYTES)
#define SM_BL       (2 * A_MAT_BYTES + B_MAT_BYTES)
#define STAGE_BYTES (2 * A_MAT_BYTES + 2 * B_MAT_BYTES)   // 61440
#define SMEM_GEMM   (3 * STAGE_BYTES)                     // 184320
#define KSTEPS      (K_DIM / BK)            // 128

#define CP_COMMIT() asm volatile("cp.async.commit_group;\n" ::: "memory")
#define CP_WAIT(n)  asm volatile("cp.async.wait_group %0;\n" :: "n"(n) : "memory")

static __device__ __forceinline__ void cp16(uint32_t dst, const void* src) {
    asm volatile("cp.async.cg.shared.global [%0], [%1], 16;\n" :: "r"(dst), "l"(src));
}

#define LDSM4(r0, r1, r2, r3, addr) \
    asm volatile("ldmatrix.sync.aligned.m8n8.x4.shared.b16 {%0,%1,%2,%3}, [%4];" \
                 : "=r"(r0), "=r"(r1), "=r"(r2), "=r"(r3) : "r"(addr))

#define MMA_BF16(d, a0, a1, a2, a3, b0, b1) \
    asm volatile("mma.sync.aligned.m16n8k16.row.col.f32.bf16.bf16.f32 " \
                 "{%0,%1,%2,%3}, {%4,%5,%6,%7}, {%8,%9}, {%0,%1,%2,%3};" \
                 : "+f"((d)[0]), "+f"((d)[1]), "+f"((d)[2]), "+f"((d)[3]) \
                 : "r"(a0), "r"(a1), "r"(a2), "r"(a3), "r"(b0), "r"(b1))

static __device__ __forceinline__ void load_stage(
    uint32_t sb, int slot, int tid,
    const char* gah, const char* gal, const char* gbh, const char* gbl, int kstep) {
    uint32_t base = sb + (uint32_t)slot * STAGE_BYTES;
    size_t kbyte = (size_t)kstep * (BK * 2);
    // A: 256 rows x 64B = 1024 chunks of 16B per matrix (2 per thread)
    #pragma unroll
    for (int i = 0; i < 2; ++i) {
        int c = tid + i * 512;
        int row = c >> 2, colb = (c & 3) * 16;
        uint32_t soff = (uint32_t)row * ROW_BYTES + colb;
        size_t goff = (size_t)row * (K_DIM * 2) + kbyte + colb;
        cp16(base + SM_AH + soff, gah + goff);
        cp16(base + SM_AL + soff, gal + goff);
    }
    // B: 128 rows x 64B = 512 chunks per matrix (1 per thread)
    {
        int row = tid >> 2, colb = (tid & 3) * 16;
        uint32_t soff = (uint32_t)row * ROW_BYTES + colb;
        size_t goff = (size_t)row * (K_DIM * 2) + kbyte + colb;
        cp16(base + SM_BH + soff, gbh + goff);
        cp16(base + SM_BL + soff, gbl + goff);
    }
}

__global__ void __launch_bounds__(512, 1)
k_gemm(const float* __restrict__ bias, float* __restrict__ outp) {
    extern __shared__ char dsmem[];
    uint32_t sb;
    asm("{ .reg .u64 t; cvta.to.shared.u64 t, %1; cvt.u32.u64 %0, t; }"
        : "=r"(sb) : "l"(dsmem));

    const int tid  = threadIdx.x;
    const int wid  = tid >> 5;
    const int lane = tid & 31;
    const int bx = blockIdx.x;               // N tile (0..31)
    const int by = blockIdx.y;               // M tile (0..31)
    const int wm = wid >> 2;                 // 0..3  (64-row slice)
    const int wn = wid & 3;                  // 0..3  (32-col slice)

    const char* gah = (const char*)(g_ah + (size_t)by * 256 * K_DIM);
    const char* gal = (const char*)(g_al + (size_t)by * 256 * K_DIM);
    const char* gbh = (const char*)(g_bh + (size_t)bx * 128 * K_DIM);
    const char* gbl = (const char*)(g_bl + (size_t)bx * 128 * K_DIM);

    // ldmatrix lane offsets
    uint32_t offA[4];
    {
        int arow = wm * 64 + (lane & 15);
        int abyte = (lane >> 4) * 16;
        #pragma unroll
        for (int mt = 0; mt < 4; ++mt)
            offA[mt] = (uint32_t)(arow + mt * 16) * ROW_BYTES + abyte;
    }
    uint32_t offB[2];
    {
        int brow_lo = ((lane >> 4) << 3) + (lane & 7);
        int bbyte = ((lane >> 3) & 1) * 16;
        #pragma unroll
        for (int p = 0; p < 2; ++p)
            offB[p] = (uint32_t)(wn * 32 + p * 16 + brow_lo) * ROW_BYTES + bbyte;
    }

    float acc[4][4][4];
    #pragma unroll
    for (int i = 0; i < 4; ++i)
        #pragma unroll
        for (int j = 0; j < 4; ++j)
            #pragma unroll
            for (int e = 0; e < 4; ++e) acc[i][j][e] = 0.0f;

    load_stage(sb, 0, tid, gah, gal, gbh, gbl, 0);
    CP_COMMIT();
    load_stage(sb, 1, tid, gah, gal, gbh, gbl, 1);
    CP_COMMIT();

    int slot = 0;
    #pragma unroll 1
    for (int s = 0; s < KSTEPS; ++s) {
        CP_WAIT(1);                 // stage s resident; s+1 may still be in flight
        __syncthreads();            // all threads done with slot reused below

        if (s + 2 < KSTEPS) {       // prefetch distance 2 into the freed slot
            int ns = slot + 2; if (ns >= 3) ns -= 3;
            load_stage(sb, ns, tid, gah, gal, gbh, gbl, s + 2);
            CP_COMMIT();
        }

        uint32_t mbase = sb + (uint32_t)slot * STAGE_BYTES;
        #pragma unroll
        for (int ks = 0; ks < 2; ++ks) {
            uint32_t kb = (uint32_t)ks * 32;
            uint32_t ah[4][4], al[4][4];
            #pragma unroll
            for (int mt = 0; mt < 4; ++mt) {
                uint32_t a = mbase + offA[mt] + kb;
                LDSM4(ah[mt][0], ah[mt][1], ah[mt][2], ah[mt][3], a + SM_AH);
                LDSM4(al[mt][0], al[mt][1], al[mt][2], al[mt][3], a + SM_AL);
            }
            #pragma unroll
            for (int p = 0; p < 2; ++p) {
                uint32_t bh[4], bl[4];
                uint32_t b = mbase + offB[p] + kb;
                LDSM4(bh[0], bh[1], bh[2], bh[3], b + SM_BH);
                LDSM4(bl[0], bl[1], bl[2], bl[3], b + SM_BL);
                #pragma unroll
                for (int mt = 0; mt < 4; ++mt) {
                    float* d0 = acc[mt][2 * p];
                    float* d1 = acc[mt][2 * p + 1];
                    MMA_BF16(d0, ah[mt][0], ah[mt][1], ah[mt][2], ah[mt][3], bh[0], bh[1]);
                    MMA_BF16(d1, ah[mt][0], ah[mt][1], ah[mt][2], ah[mt][3], bh[2], bh[3]);
                    MMA_BF16(d0, ah[mt][0], ah[mt][1], ah[mt][2], ah[mt][3], bl[0], bl[1]);
                    MMA_BF16(d1, ah[mt][0], ah[mt][1], ah[mt][2], ah[mt][3], bl[2], bl[3]);
                    MMA_BF16(d0, al[mt][0], al[mt][1], al[mt][2], al[mt][3], bh[0], bh[1]);
                    MMA_BF16(d1, al[mt][0], al[mt][1], al[mt][2], al[mt][3], bh[2], bh[3]);
                }
            }
        }
        if (++slot >= 3) slot = 0;
    }

    // ---- epilogue: add bias, store fp32 ----
    #pragma unroll
    for (int nt = 0; nt < 4; ++nt) {
        int col = bx * 128 + wn * 32 + nt * 8 + (lane & 3) * 2;
        float2 bv = *(const float2*)(bias + col);
        #pragma unroll
        for (int mt = 0; mt < 4; ++mt) {
            int r0 = by * 256 + wm * 64 + mt * 16 + (lane >> 2);
            float2 o0, o1;
            o0.x = acc[mt][nt][0] + bv.x; o0.y = acc[mt][nt][1] + bv.y;
            o1.x = acc[mt][nt][2] + bv.x; o1.y = acc[mt][nt][3] + bv.y;
            *(float2*)(outp + (size_t)r0 * N_DIM + col)       = o0;
            *(float2*)(outp + (size_t)(r0 + 8) * N_DIM + col) = o1;
        }
    }
}

// ===========================================================================
extern "C" void kernel_launch(void* const* d_in, const int* in_sizes, int n_in,
                              void* d_out, int out_size) {
    const float* x    = (const float*)d_in[0];
    const float* w    = (const float*)d_in[1];
    const float* bias = (const float*)d_in[2];
    const float* s    = (const float*)d_in[3];
    float* out = (float*)d_out;

    k_init<<<1, 256>>>();
    for (int shift = 24; shift >= 0; shift -= 8) {
        k_hist<<<1024, 256>>>((const float4*)s, NTOT / 4, shift);
        k_pick<<<1, 1>>>(shift);
    }
    k_gather<<<1024, 256>>>((const float4*)s, NTOT / 4);
    k_select_cut<<<1, 256>>>();

    k_split_w<<<2048, 256>>>((const float4*)w, (const float4*)s, NTOT / 4);
    k_split_a<<<4096, 256>>>((const float4*)x, (M_DIM * K_DIM) / 4);

    cudaFuncSetAttribute(k_gemm, cudaFuncAttributeMaxDynamicSharedMemorySize, SMEM_GEMM);
    dim3 grid(N_DIM / 128, M_DIM / 256);   // 32 x 32
    k_gemm<<<grid, 512, SMEM_GEMM>>>(bias, out);
}

// round 5
// speedup vs baseline: 3.3479x; 1.2216x over previous
#include <cuda_runtime.h>
#include <cuda_bf16.h>
#include <cstdint>

// ===========================================================================
// WeightPopupLayer: out = x @ (W * topk_mask(|scores|, 50%)).T + bias
// Round 5: bf16 hi/lo 3-term mma.sync GEMM fed by cp.async.bulk (UBLKCP)
// from a tile-blocked pre-swizzled GMEM scratch layout; 4-stage mbarrier
// ring; CTA raster swizzle for L2 reuse.
// ===========================================================================

#define NTOT   (4096 * 4096)
#define JRANK  8388608u
#define EQ_CAP (1 << 20)

#define M_DIM 8192
#define N_DIM 4096
#define K_DIM 4096

// Blocked scratch layouts:
//   A (x):   g_ah/g_al  [by=32][ks=128] blocks of 256 rows x 64B = 16384 B
//   B (W):   g_bh/g_bl  [bx=32][ks=128] blocks of 128 rows x 64B =  8192 B
// In-block address for (row, chunk cs in 0..3, byte b in 0..15):
//   off = row*64 + ((cs ^ ((row>>1)&3)) << 4) + b     (bank-conflict-free ldsm)
__device__ __align__(16) __nv_bfloat16 g_ah[M_DIM * K_DIM];
__device__ __align__(16) __nv_bfloat16 g_al[M_DIM * K_DIM];
__device__ __align__(16) __nv_bfloat16 g_bh[N_DIM * K_DIM];
__device__ __align__(16) __nv_bfloat16 g_bl[N_DIM * K_DIM];

__device__ unsigned g_hist[256];
__device__ unsigned g_prefix;
__device__ unsigned g_rank;
__device__ unsigned g_neq;
__device__ unsigned g_idxcut;
__device__ unsigned g_eqidx[EQ_CAP];

static __device__ __forceinline__ unsigned abs_bits(float v) {
    return __float_as_uint(fabsf(v));
}

// ======================= selection kernels =================================
__global__ void k_init() {
    int t = threadIdx.x;
    if (t < 256) g_hist[t] = 0;
    if (t == 0) { g_prefix = 0u; g_rank = JRANK; g_neq = 0u; g_idxcut = 0u; }
}

__global__ void k_hist(const float4* __restrict__ s4, int n4, int shift) {
    __shared__ unsigned sh[256];
    if (threadIdx.x < 256) sh[threadIdx.x] = 0;
    __syncthreads();
    const unsigned pref = g_prefix;
    const unsigned mask = (shift == 24) ? 0u : (0xFFFFFFFFu << (shift + 8));
    int stride = blockDim.x * gridDim.x;
    for (int i = blockIdx.x * blockDim.x + threadIdx.x; i < n4; i += stride) {
        float4 v = s4[i];
        unsigned b;
        b = abs_bits(v.x); if ((b & mask) == pref) atomicAdd(&sh[(b >> shift) & 255], 1u);
        b = abs_bits(v.y); if ((b & mask) == pref) atomicAdd(&sh[(b >> shift) & 255], 1u);
        b = abs_bits(v.z); if ((b & mask) == pref) atomicAdd(&sh[(b >> shift) & 255], 1u);
        b = abs_bits(v.w); if ((b & mask) == pref) atomicAdd(&sh[(b >> shift) & 255], 1u);
    }
    __syncthreads();
    if (threadIdx.x < 256 && sh[threadIdx.x])
        atomicAdd(&g_hist[threadIdx.x], sh[threadIdx.x]);
}

__global__ void k_pick(int shift) {
    unsigned r = g_rank, cum = 0;
    #pragma unroll 1
    for (int b = 0; b < 256; ++b) {
        unsigned c = g_hist[b];
        if (cum + c > r) { g_prefix |= ((unsigned)b) << shift; g_rank = r - cum; break; }
        cum += c;
    }
    for (int b = 0; b < 256; ++b) g_hist[b] = 0;
}

__global__ void k_gather(const float4* __restrict__ s4, int n4) {
    const unsigned tb = g_prefix;
    int stride = blockDim.x * gridDim.x;
    for (int i = blockIdx.x * blockDim.x + threadIdx.x; i < n4; i += stride) {
        float4 v = s4[i];
        unsigned base = (unsigned)i << 2;
        if (abs_bits(v.x) == tb) { unsigned p = atomicAdd(&g_neq, 1u); if (p < EQ_CAP) g_eqidx[p] = base + 0; }
        if (abs_bits(v.y) == tb) { unsigned p = atomicAdd(&g_neq, 1u); if (p < EQ_CAP) g_eqidx[p] = base + 1; }
        if (abs_bits(v.z) == tb) { unsigned p = atomicAdd(&g_neq, 1u); if (p < EQ_CAP) g_eqidx[p] = base + 2; }
        if (abs_bits(v.w) == tb) { unsigned p = atomicAdd(&g_neq, 1u); if (p < EQ_CAP) g_eqidx[p] = base + 3; }
    }
}

__global__ void k_select_cut() {
    unsigned m = min(g_neq, (unsigned)EQ_CAP);
    unsigned d = g_rank;
    if (threadIdx.x == 0) {
        if (d == 0u) g_idxcut = 0u;
        else if (d >= m) g_idxcut = 0xFFFFFFFFu;
    }
    if (d == 0u || d >= m) return;
    for (unsigned e = threadIdx.x; e < m; e += blockDim.x) {
        unsigned v = g_eqidx[e];
        unsigned rank = 0;
        for (unsigned f = 0; f < m; ++f) rank += (g_eqidx[f] < v);
        if (rank == d) g_idxcut = v;
    }
}

// ======================= split kernels (blocked layout) ====================
static __device__ __forceinline__ void split1(float f, unsigned short& h, unsigned short& l) {
    __nv_bfloat16 hh = __float2bfloat16(f);
    __nv_bfloat16 ll = __float2bfloat16(f - __bfloat162float(hh));
    h = __bfloat16_as_ushort(hh);
    l = __bfloat16_as_ushort(ll);
}

static __device__ __forceinline__ uint2 pack4(const float* f) {
    unsigned short h[4], l[4];
    #pragma unroll
    for (int c = 0; c < 4; ++c) split1(f[c], h[c], l[c]);
    uint2 r;
    r.x = (unsigned)h[0] | ((unsigned)h[1] << 16);
    r.y = (unsigned)h[2] | ((unsigned)h[3] << 16);
    // lo halves returned via second call pattern; see callers
    (void)l;
    return r;
}

// masked W -> blocked bf16 hi/lo (128-row blocks, 8192 B)
__global__ void k_split_w(const float4* __restrict__ w4, const float4* __restrict__ s4, int n4) {
    const unsigned tb  = g_prefix;
    const unsigned cut = g_idxcut;
    int stride = blockDim.x * gridDim.x;
    for (int i = blockIdx.x * blockDim.x + threadIdx.x; i < n4; i += stride) {
        float4 wv = w4[i], sv = s4[i];
        unsigned fi = (unsigned)i << 2;
        float f[4];
        unsigned b0 = abs_bits(sv.x), b1 = abs_bits(sv.y), b2 = abs_bits(sv.z), b3 = abs_bits(sv.w);
        f[0] = (b0 > tb || (b0 == tb && fi + 0 >= cut)) ? wv.x : 0.0f;
        f[1] = (b1 > tb || (b1 == tb && fi + 1 >= cut)) ? wv.y : 0.0f;
        f[2] = (b2 > tb || (b2 == tb && fi + 2 >= cut)) ? wv.z : 0.0f;
        f[3] = (b3 > tb || (b3 == tb && fi + 3 >= cut)) ? wv.w : 0.0f;
        unsigned short h[4], l[4];
        #pragma unroll
        for (int c = 0; c < 4; ++c) split1(f[c], h[c], l[c]);
        uint2 ph, pl;
        ph.x = (unsigned)h[0] | ((unsigned)h[1] << 16);
        ph.y = (unsigned)h[2] | ((unsigned)h[3] << 16);
        pl.x = (unsigned)l[0] | ((unsigned)l[1] << 16);
        pl.y = (unsigned)l[2] | ((unsigned)l[3] << 16);
        unsigned row = fi >> 12, k = fi & 4095;
        unsigned bx = row >> 7, rl = row & 127;
        unsigned ks = k >> 5, kl = k & 31;
        unsigned cs = kl >> 3;
        size_t   blk = (size_t)(bx * 128 + ks) << 13;
        unsigned off = rl * 64 + (((cs ^ ((rl >> 1) & 3))) << 4) + (kl & 7) * 2;
        *(uint2*)((char*)g_bh + blk + off) = ph;
        *(uint2*)((char*)g_bl + blk + off) = pl;
    }
}

// x -> blocked bf16 hi/lo (256-row blocks, 16384 B)
__global__ void k_split_a(const float4* __restrict__ x4, int n4) {
    int stride = blockDim.x * gridDim.x;
    for (int i = blockIdx.x * blockDim.x + threadIdx.x; i < n4; i += stride) {
        float4 v = x4[i];
        float f[4] = {v.x, v.y, v.z, v.w};
        unsigned short h[4], l[4];
        #pragma unroll
        for (int c = 0; c < 4; ++c) split1(f[c], h[c], l[c]);
        uint2 ph, pl;
        ph.x = (unsigned)h[0] | ((unsigned)h[1] << 16);
        ph.y = (unsigned)h[2] | ((unsigned)h[3] << 16);
        pl.x = (unsigned)l[0] | ((unsigned)l[1] << 16);
        pl.y = (unsigned)l[2] | ((unsigned)l[3] << 16);
        unsigned fi = (unsigned)i << 2;
        unsigned row = fi >> 12, k = fi & 4095;
        unsigned by = row >> 8, rl = row & 255;
        unsigned ks = k >> 5, kl = k & 31;
        unsigned cs = kl >> 3;
        size_t   blk = (size_t)(by * 128 + ks) << 14;
        unsigned off = rl * 64 + (((cs ^ ((rl >> 1) & 3))) << 4) + (kl & 7) * 2;
        *(uint2*)((char*)g_ah + blk + off) = ph;
        *(uint2*)((char*)g_al + blk + off) = pl;
    }
}

// ======================= GEMM ==============================================
// CTA tile 256(M) x 128(N), BK=32, 512 threads = 16 warps (4x4), warp 64x32.
// 4-stage ring of 48 KB stages filled by cp.async.bulk, mbarrier completion.

#define STAGES      4
#define STAGE_BYTES 49152
#define SM_AH       0
#define SM_AL       16384
#define SM_BH       32768
#define SM_BL       40960
#define SMEM_GEMM   (STAGES * STAGE_BYTES)    // 196608
#define KSTEPS      (K_DIM / 32)              // 128

#define LDSM4(r0, r1, r2, r3, addr) \
    asm volatile("ldmatrix.sync.aligned.m8n8.x4.shared.b16 {%0,%1,%2,%3}, [%4];" \
                 : "=r"(r0), "=r"(r1), "=r"(r2), "=r"(r3) : "r"(addr))

#define MMA_BF16(d, a0, a1, a2, a3, b0, b1) \
    asm volatile("mma.sync.aligned.m16n8k16.row.col.f32.bf16.bf16.f32 " \
                 "{%0,%1,%2,%3}, {%4,%5,%6,%7}, {%8,%9}, {%0,%1,%2,%3};" \
                 : "+f"((d)[0]), "+f"((d)[1]), "+f"((d)[2]), "+f"((d)[3]) \
                 : "r"(a0), "r"(a1), "r"(a2), "r"(a3), "r"(b0), "r"(b1))

#define MBARRIER_INIT(mbar, cnt) \
    asm volatile("mbarrier.init.shared.b64 [%0], %1;" :: "r"((uint32_t)(mbar)), "r"((uint32_t)(cnt)) : "memory")
#define MBARRIER_EXPECT_TX(mbar, tx) \
    asm volatile("mbarrier.arrive.expect_tx.shared.b64 _, [%0], %1;" :: "r"((uint32_t)(mbar)), "r"((uint32_t)(tx)) : "memory")

#define MBARRIER_WAIT_PARITY(mbar_smem_addr, phase_parity) do { \
    uint32_t _mbar = (uint32_t)(mbar_smem_addr); \
    uint32_t _parity = (uint32_t)(phase_parity); \
    uint32_t _done; \
    asm volatile("{\n\t.reg .pred p;\n\t" \
        "mbarrier.try_wait.parity.acquire.cta.shared::cta.b64 p, [%1], %2;\n\t" \
        "selp.b32 %0, 1, 0, p;\n\t}" \
        : "=r"(_done) : "r"(_mbar), "r"(_parity) : "memory"); \
    if (!_done) { \
        asm volatile("{\n\t.reg .pred P1;\n\t" \
            "WAIT_LOOP_%=:\n\t" \
            "mbarrier.try_wait.parity.acquire.cta.shared::cta.b64 P1, [%0], %1, 0x989680;\n\t" \
            "@P1 bra.uni WAIT_DONE_%=;\n\t" \
            "bra.uni WAIT_LOOP_%=;\n\t" \
            "WAIT_DONE_%=:\n\t}" \
            :: "r"(_mbar), "r"(_parity) : "memory"); \
    } \
} while (0)

static __device__ __forceinline__ void bulk_g2s(uint32_t dst, const void* src,
                                                uint32_t bytes, uint32_t mbar) {
    asm volatile(
        "cp.async.bulk.shared::cluster.global.mbarrier::complete_tx::bytes [%0], [%1], %2, [%3];"
        :: "r"(dst), "l"(src), "r"(bytes), "r"(mbar) : "memory");
}

__global__ void __launch_bounds__(512, 1)
k_gemm(const float* __restrict__ bias, float* __restrict__ outp) {
    extern __shared__ __align__(16) char dsmem[];
    __shared__ __align__(8) unsigned long long s_mbar[STAGES];

    uint32_t sb, mb;
    asm("{ .reg .u64 t; cvta.to.shared.u64 t, %1; cvt.u32.u64 %0, t; }" : "=r"(sb) : "l"(dsmem));
    asm("{ .reg .u64 t; cvta.to.shared.u64 t, %1; cvt.u32.u64 %0, t; }" : "=r"(mb) : "l"(&s_mbar[0]));

    const int tid  = threadIdx.x;
    const int wid  = tid >> 5;
    const int lane = tid & 31;

    // raster swizzle: 1024 blocks = 4 groups x (8 by x 32 bx)
    const int bid = blockIdx.x;
    const int by  = (bid >> 8) * 8 + (bid & 7);
    const int bx  = (bid >> 3) & 31;

    const int wm = wid >> 2;                 // 0..3
    const int wn = wid & 3;                  // 0..3

    const char* gah = (const char*)g_ah + ((size_t)by * 128 << 14);
    const char* gal = (const char*)g_al + ((size_t)by * 128 << 14);
    const char* gbh = (const char*)g_bh + ((size_t)bx * 128 << 13);
    const char* gbl = (const char*)g_bl + ((size_t)bx * 128 << 13);

    // per-lane ldsm addressing
    uint32_t rowOffA[4], swzA[4];
    const uint32_t hiA = (lane >> 4) & 1;
    {
        int arow = wm * 64 + (lane & 15);
        #pragma unroll
        for (int mt = 0; mt < 4; ++mt) {
            int r = arow + mt * 16;
            rowOffA[mt] = (uint32_t)r * 64;
            swzA[mt]    = ((uint32_t)r >> 1) & 3;
        }
    }
    uint32_t rowOffB[2], swzB[2];
    const uint32_t hiB = (lane >> 3) & 1;
    {
        int brow_lo = ((lane >> 4) << 3) + (lane & 7);
        #pragma unroll
        for (int p = 0; p < 2; ++p) {
            int r = wn * 32 + p * 16 + brow_lo;
            rowOffB[p] = (uint32_t)r * 64;
            swzB[p]    = ((uint32_t)r >> 1) & 3;
        }
    }

    if (tid == 0) {
        #pragma unroll
        for (int s = 0; s < STAGES; ++s) MBARRIER_INIT(mb + s * 8, 1);
    }
    __syncthreads();

    if (tid == 0) {
        #pragma unroll
        for (int s = 0; s < 3; ++s) {
            uint32_t mbar = mb + s * 8;
            uint32_t dst  = sb + s * STAGE_BYTES;
            MBARRIER_EXPECT_TX(mbar, STAGE_BYTES);
            bulk_g2s(dst + SM_AH, gah + ((size_t)s << 14), 16384, mbar);
            bulk_g2s(dst + SM_AL, gal + ((size_t)s << 14), 16384, mbar);
            bulk_g2s(dst + SM_BH, gbh + ((size_t)s << 13), 8192,  mbar);
            bulk_g2s(dst + SM_BL, gbl + ((size_t)s << 13), 8192,  mbar);
        }
    }

    float acc[4][4][4];
    #pragma unroll
    for (int i = 0; i < 4; ++i)
        #pragma unroll
        for (int j = 0; j < 4; ++j)
            #pragma unroll
            for (int e = 0; e < 4; ++e) acc[i][j][e] = 0.0f;

    #pragma unroll 1
    for (int s = 0; s < KSTEPS; ++s) {
        const int slot = s & 3;
        MBARRIER_WAIT_PARITY(mb + slot * 8, (s >> 2) & 1);

        uint32_t sbase = sb + (uint32_t)slot * STAGE_BYTES;
        #pragma unroll
        for (int ks = 0; ks < 2; ++ks) {
            const uint32_t ks2 = (uint32_t)ks << 1;
            uint32_t ah[4][4], al[4][4];
            #pragma unroll
            for (int mt = 0; mt < 4; ++mt) {
                uint32_t a = sbase + rowOffA[mt] + (((ks2 | hiA) ^ swzA[mt]) << 4);
                LDSM4(ah[mt][0], ah[mt][1], ah[mt][2], ah[mt][3], a + SM_AH);
                LDSM4(al[mt][0], al[mt][1], al[mt][2], al[mt][3], a + SM_AL);
            }
            #pragma unroll
            for (int p = 0; p < 2; ++p) {
                uint32_t bh[4], bl[4];
                uint32_t b = sbase + rowOffB[p] + (((ks2 | hiB) ^ swzB[p]) << 4);
                LDSM4(bh[0], bh[1], bh[2], bh[3], b + SM_BH);
                LDSM4(bl[0], bl[1], bl[2], bl[3], b + SM_BL);
                #pragma unroll
                for (int mt = 0; mt < 4; ++mt) {
                    float* d0 = acc[mt][2 * p];
                    float* d1 = acc[mt][2 * p + 1];
                    MMA_BF16(d0, ah[mt][0], ah[mt][1], ah[mt][2], ah[mt][3], bh[0], bh[1]);
                    MMA_BF16(d1, ah[mt][0], ah[mt][1], ah[mt][2], ah[mt][3], bh[2], bh[3]);
                    MMA_BF16(d0, ah[mt][0], ah[mt][1], ah[mt][2], ah[mt][3], bl[0], bl[1]);
                    MMA_BF16(d1, ah[mt][0], ah[mt][1], ah[mt][2], ah[mt][3], bl[2], bl[3]);
                    MMA_BF16(d0, al[mt][0], al[mt][1], al[mt][2], al[mt][3], bh[0], bh[1]);
                    MMA_BF16(d1, al[mt][0], al[mt][1], al[mt][2], al[mt][3], bh[2], bh[3]);
                }
            }
        }

        __syncthreads();   // all threads done with slot (s+3)&3's previous use
        if (tid == 0 && s + 3 < KSTEPS) {
            const int ns = s + 3;
            const int nslot = ns & 3;
            uint32_t mbar = mb + nslot * 8;
            uint32_t dst  = sb + (uint32_t)nslot * STAGE_BYTES;
            MBARRIER_EXPECT_TX(mbar, STAGE_BYTES);
            bulk_g2s(dst + SM_AH, gah + ((size_t)ns << 14), 16384, mbar);
            bulk_g2s(dst + SM_AL, gal + ((size_t)ns << 14), 16384, mbar);
            bulk_g2s(dst + SM_BH, gbh + ((size_t)ns << 13), 8192,  mbar);
            bulk_g2s(dst + SM_BL, gbl + ((size_t)ns << 13), 8192,  mbar);
        }
    }

    // ---- epilogue: add bias, store fp32 ----
    #pragma unroll
    for (int nt = 0; nt < 4; ++nt) {
        int col = bx * 128 + wn * 32 + nt * 8 + (lane & 3) * 2;
        float2 bv = *(const float2*)(bias + col);
        #pragma unroll
        for (int mt = 0; mt < 4; ++mt) {
            int r0 = by * 256 + wm * 64 + mt * 16 + (lane >> 2);
            float2 o0, o1;
            o0.x = acc[mt][nt][0] + bv.x; o0.y = acc[mt][nt][1] + bv.y;
            o1.x = acc[mt][nt][2] + bv.x; o1.y = acc[mt][nt][3] + bv.y;
            *(float2*)(outp + (size_t)r0 * N_DIM + col)       = o0;
            *(float2*)(outp + (size_t)(r0 + 8) * N_DIM + col) = o1;
        }
    }
}

// ===========================================================================
extern "C" void kernel_launch(void* const* d_in, const int* in_sizes, int n_in,
                              void* d_out, int out_size) {
    const float* x    = (const float*)d_in[0];
    const float* w    = (const float*)d_in[1];
    const float* bias = (const float*)d_in[2];
    const float* s    = (const float*)d_in[3];
    float* out = (float*)d_out;

    k_init<<<1, 256>>>();
    for (int shift = 24; shift >= 0; shift -= 8) {
        k_hist<<<1024, 256>>>((const float4*)s, NTOT / 4, shift);
        k_pick<<<1, 1>>>(shift);
    }
    k_gather<<<1024, 256>>>((const float4*)s, NTOT / 4);
    k_select_cut<<<1, 256>>>();

    k_split_w<<<2048, 256>>>((const float4*)w, (const float4*)s, NTOT / 4);
    k_split_a<<<4096, 256>>>((const float4*)x, (M_DIM * K_DIM) / 4);

    cudaFuncSetAttribute(k_gemm, cudaFuncAttributeMaxDynamicSharedMemorySize, SMEM_GEMM);
    k_gemm<<<1024, 512, SMEM_GEMM>>>(bias, out);
}